// round 15
// baseline (speedup 1.0000x reference)
#include <cuda_runtime.h>
#include <cstdint>

// Chamfer distance, B=4,S=4 pairs, N=M=4096 Gaussian 3D points.
// Warp-uniform 1-D sorted-window exact NN, SLAB-staged for occupancy:
//  1) build_sorted: counting-sort the 32 lists by x into 256 bins over
//     [-5,5]; packed 32B records {x0,x1,y0,y1,z0,z1,h0,h1} (h=0.5|p|^2)
//     + u16 bin starts. Zeroes d_out (block 0).
//  2) chamfer_query: block owns 256 consecutive sorted queries. It
//     stages ONLY the target slab [firstBin-8, lastBin+8] (<=2048 pts,
//     <=32KB) -> 6 blocks/SM resident (vs 3 at full-list staging).
//     Warp-union window scan (2xLDS.128 + 3xFMA2 + 2xFMNMX per record,
//     unroll 4); ballot-driven exact expansion; slices outside the
//     staged slab fall back to uniform-address LDG on g_packed (rare).

#define BDIM 4
#define SDIM 4
#define NPAIRS 16
#define NB 256
#define MAXPTS 4096
#define NREC ((MAXPTS + 8) / 2)   /* 2052 records of 2 points */
#define GRIDMIN (-5.0f)
#define BW 0.0390625f             /* 10/256 */
#define INVBW 25.6f
#define QTHREADS 256
#define SCAP 2048                 /* staged points cap (32KB) */

__device__ float g_packed[2 * NPAIRS][NREC * 8];
__device__ unsigned short g_start[2 * NPAIRS][NB + 1];

__device__ __forceinline__ uint64_t fma2(uint64_t a, uint64_t b, uint64_t c) {
    uint64_t d;
    asm("fma.rn.f32x2 %0, %1, %2, %3;" : "=l"(d) : "l"(a), "l"(b), "l"(c));
    return d;
}
__device__ __forceinline__ uint64_t pack2(float lo, float hi) {
    uint64_t d;
    asm("mov.b64 %0, {%1, %2};" : "=l"(d) : "f"(lo), "f"(hi));
    return d;
}
__device__ __forceinline__ void unpack2(uint64_t v, float& lo, float& hi) {
    asm("mov.b64 {%0, %1}, %2;" : "=f"(lo), "=f"(hi) : "l"(v));
}

// ---------------- counting sort by x into 256 bins ----------------
__global__ void build_sorted(const float* __restrict__ outp,
                             const float* __restrict__ tgtp,
                             int Nq, int Mt, float* __restrict__ out) {
    const int list = blockIdx.x;            // 0..31
    const int set = list >> 4, pair = list & 15;
    const float* pts = set ? tgtp : outp;
    const int n = set ? Mt : Nq;
    const float* base = pts + (size_t)pair * n * 3;

    if (list == 0 && threadIdx.x < BDIM * SDIM) out[threadIdx.x] = 0.f;

    __shared__ int cnt[NB];
    const int t = threadIdx.x;              // 256 threads

    cnt[t] = 0;
    __syncthreads();

    for (int i = t; i < n; i += NB) {
        float x = base[3 * i];
        int b = min(max(__float2int_rd((x - GRIDMIN) * INVBW), 0), NB - 1);
        atomicAdd(&cnt[b], 1);
    }
    __syncthreads();

    int v = cnt[t];
    __syncthreads();
#pragma unroll
    for (int off = 1; off < NB; off <<= 1) {
        int u = (t >= off) ? cnt[t - off] : 0;
        __syncthreads();
        cnt[t] += u;
        __syncthreads();
    }
    int start = cnt[t] - v;  // exclusive

    g_start[list][t] = (unsigned short)start;
    if (t == 0) g_start[list][NB] = (unsigned short)n;

    __syncthreads();
    cnt[t] = start;
    __syncthreads();

    for (int i = t; i < n; i += NB) {
        float x = base[3 * i], y = base[3 * i + 1], z = base[3 * i + 2];
        int b = min(max(__float2int_rd((x - GRIDMIN) * INVBW), 0), NB - 1);
        int idx = atomicAdd(&cnt[b], 1);
        float* rec = &g_packed[list][(idx >> 1) * 8];
        int s = idx & 1;
        rec[0 + s] = x;
        rec[2 + s] = y;
        rec[4 + s] = z;
        rec[6 + s] = 0.5f * (x * x + y * y + z * z);
    }
    // sentinel pad points [n, 2*NREC)
    for (int i = n + t; i < 2 * NREC; i += NB) {
        float* rec = &g_packed[list][(i >> 1) * 8];
        int s = i & 1;
        rec[0 + s] = 1e30f;
        rec[2 + s] = 0.f;
        rec[4 + s] = 0.f;
        rec[6 + s] = 3.0e37f;
    }
}

// ---------------- query ----------------
extern __shared__ uint4 srecs4[];   // SCAP points = SCAP uint4 (32KB)

#define SCAN_BODY(Aname, Bname)                                            \
    do {                                                                   \
        uint64_t tv = fma2(nx, (Aname).x, (Bname).y);                      \
        tv = fma2(ny, (Aname).y, tv);                                      \
        tv = fma2(nz, (Bname).x, tv);                                      \
        float lo, hi;                                                      \
        unpack2(tv, lo, hi);                                               \
        mlo = fminf(mlo, lo);                                              \
        mhi = fminf(mhi, hi);                                              \
    } while (0)

// scan LOCAL (staged) even point range [a,b), indices rebased to slab
__device__ __forceinline__ void scan_sm(
    int a, int b, uint64_t nx, uint64_t ny, uint64_t nz,
    const ulonglong2* __restrict__ recs, float& mlo, float& mhi) {
    const int j0 = a >> 1, j1 = b >> 1;
#pragma unroll 4
    for (int j = j0; j < j1; j++) {
        ulonglong2 A = recs[2 * j];      // {x2, y2}
        ulonglong2 B = recs[2 * j + 1];  // {z2, h2}
        SCAN_BODY(A, B);
    }
}

// scan GLOBAL even point range [a,b) via uniform-address LDG (rare)
__device__ __forceinline__ void scan_gl(
    int a, int b, uint64_t nx, uint64_t ny, uint64_t nz,
    const ulonglong2* __restrict__ recs, float& mlo, float& mhi) {
    const int j0 = a >> 1, j1 = b >> 1;
#pragma unroll 1
    for (int j = j0; j < j1; j++) {
        ulonglong2 A = __ldg(&recs[2 * j]);
        ulonglong2 B = __ldg(&recs[2 * j + 1]);
        SCAN_BODY(A, B);
    }
}

__global__ __launch_bounds__(QTHREADS, 6)
void chamfer_query(int Nq, int Mt, float* __restrict__ out) {
    const int dir = blockIdx.z;             // 0: out->tgt, 1: tgt->out
    const int pair = blockIdx.y;
    const int qlist = (dir ? NPAIRS : 0) + pair;      // own (sorted) set
    const int tlist = (dir ? 0 : NPAIRS) + pair;      // other set
    const int nq = dir ? Mt : Nq;

    __shared__ unsigned short sstart[NB + 1];
    __shared__ int shr[2];                  // S0, S1 (staged point range)
    __shared__ float red[QTHREADS / 32];

    for (int c = threadIdx.x; c <= NB; c += QTHREADS)
        sstart[c] = g_start[tlist][c];
    __syncthreads();

    // ---- choose staged slab from this block's query x-range ----
    const int q0 = blockIdx.x * QTHREADS;
    if (threadIdx.x == 0) {
        int S0 = 0, S1 = 0;
        if (q0 < nq) {
            int q1 = min(q0 + QTHREADS - 1, nq - 1);
            const float* qr0 = &g_packed[qlist][(q0 >> 1) * 8];
            const float* qr1 = &g_packed[qlist][(q1 >> 1) * 8];
            float x0 = qr0[0 + (q0 & 1)];
            float x1 = qr1[0 + (q1 & 1)];
            int b0 = min(max(__float2int_rd((x0 - GRIDMIN) * INVBW), 0), NB - 1);
            int b1 = min(max(__float2int_rd((x1 - GRIDMIN) * INVBW), 0), NB - 1);
            for (int m = 8; m >= 0; m--) {   // largest margin fitting SCAP
                int BL = max(b0 - m, 0);
                int BR = min(b1 + m, NB - 1);
                int a = sstart[BL] & ~1;
                int b = min(((int)sstart[BR + 1] + 1) & ~1, 2 * NREC);
                if (b - a <= SCAP || m == 0) { S0 = a; S1 = b; break; }
            }
        }
        shr[0] = S0; shr[1] = S1;
    }
    __syncthreads();
    const int S0 = shr[0], S1 = shr[1];

    // ---- stage slab records: uint4 index == point index in [S0,S1) ----
    {
        const uint4* src = (const uint4*)g_packed[tlist];
        for (int i = S0 + threadIdx.x; i < S1; i += QTHREADS)
            srecs4[i - S0] = src[i];
    }
    __syncthreads();

    const ulonglong2* recs_s = (const ulonglong2*)srecs4;
    const ulonglong2* recs_g = (const ulonglong2*)g_packed[tlist];

    const int qi = q0 + threadIdx.x;
    const bool active = (qi < nq);

    float qx = 0.f, q2 = 0.f;
    uint64_t nx = 0, ny = 0, nz = 0;
    int qb = 0x7fffffff, qb2 = -1;
    if (active) {
        const float* qr = &g_packed[qlist][(qi >> 1) * 8];
        int s = qi & 1;
        qx = qr[0 + s];
        float qy = qr[2 + s], qz = qr[4 + s];
        q2 = qx * qx + qy * qy + qz * qz;
        nx = pack2(-qx, -qx);
        ny = pack2(-qy, -qy);
        nz = pack2(-qz, -qz);
        qb = min(max(__float2int_rd((qx - GRIDMIN) * INVBW), 0), NB - 1);
        qb2 = qb;
    }
    float mlo = 3.0e37f, mhi = 3.0e37f;

    // warp-union window
    int BL = qb, BR = qb2;
#pragma unroll
    for (int off = 16; off; off >>= 1) {
        BL = min(BL, __shfl_xor_sync(0xffffffffu, BL, off));
        BR = max(BR, __shfl_xor_sync(0xffffffffu, BR, off));
    }

    if (BR >= 0) {
        BL = max(BL - 3, 0);
        BR = min(BR + 4, NB);

        int LO = sstart[BL] & ~1;
        int HI = (sstart[BR] + 1) & ~1;
        if (LO >= S0 && HI <= S1)
            scan_sm(LO - S0, HI - S0, nx, ny, nz, recs_s, mlo, mhi);
        else
            scan_gl(LO, HI, nx, ny, nz, recs_g, mlo, mhi);

        // ---- ballot-driven warp-uniform expansion ----
        for (int iter = 0; iter < NB; iter++) {
            float best = fmaxf(fmaf(2.0f, fminf(mlo, mhi), q2), 0.0f);
            float lb = fmaxf(qx - (GRIDMIN + BL * BW) - 1e-4f, 0.0f);
            float rb = fmaxf((GRIDMIN + BR * BW) - qx - 1e-4f, 0.0f);
            bool needL = active && (BL > 0)  && (lb * lb < best);
            bool needR = active && (BR < NB) && (rb * rb < best);
            unsigned anyL = __ballot_sync(0xffffffffu, needL);
            unsigned anyR = __ballot_sync(0xffffffffu, needR);
            if (!anyL && !anyR) break;
            if (anyL) {
                int nBL = BL - 1;
                int nLO = sstart[nBL] & ~1;
                if (nLO >= S0 && LO <= S1)
                    scan_sm(nLO - S0, LO - S0, nx, ny, nz, recs_s, mlo, mhi);
                else
                    scan_gl(nLO, LO, nx, ny, nz, recs_g, mlo, mhi);
                BL = nBL; LO = nLO;
            }
            if (anyR) {
                int nBR = BR + 1;
                int nHI = (sstart[nBR] + 1) & ~1;
                if (HI >= S0 && nHI <= S1)
                    scan_sm(HI - S0, nHI - S0, nx, ny, nz, recs_s, mlo, mhi);
                else
                    scan_gl(HI, nHI, nx, ny, nz, recs_g, mlo, mhi);
                BR = nBR; HI = nHI;
            }
        }
    }

    float lsum = active ? fmaxf(fmaf(2.0f, fminf(mlo, mhi), q2), 0.0f) : 0.f;

    // ---- block reduce + one atomicAdd ----
#pragma unroll
    for (int off = 16; off; off >>= 1)
        lsum += __shfl_down_sync(0xffffffffu, lsum, off);
    const int lwid = threadIdx.x >> 5;
    if ((threadIdx.x & 31) == 0) red[lwid] = lsum;
    __syncthreads();
    if (threadIdx.x == 0) {
        float tot = 0.f;
#pragma unroll
        for (int w = 0; w < QTHREADS / 32; w++) tot += red[w];
        int b = pair / SDIM;
        int s = pair % SDIM;
        atomicAdd(out + s * BDIM + b, tot / (float)nq);
    }
}

extern "C" void kernel_launch(void* const* d_in, const int* in_sizes, int n_in,
                              void* d_out, int out_size) {
    const float* outp = (const float*)d_in[0];  // [B,S,N,3]
    const float* tgtp = (const float*)d_in[1];  // [B,S,M,3]
    float* out = (float*)d_out;                  // [S,B]

    const int Nq = in_sizes[0] / (NPAIRS * 3);
    const int Mt = in_sizes[1] / (NPAIRS * 3);

    build_sorted<<<2 * NPAIRS, NB>>>(outp, tgtp, Nq, Mt, out);

    const size_t smem = (size_t)SCAP * sizeof(uint4);   // 32KB slab
    cudaFuncSetAttribute(chamfer_query,
                         cudaFuncAttributeMaxDynamicSharedMemorySize, (int)smem);

    const int maxq = Nq > Mt ? Nq : Mt;
    dim3 grid((maxq + QTHREADS - 1) / QTHREADS, NPAIRS, 2);  // 512 blocks
    chamfer_query<<<grid, QTHREADS, smem>>>(Nq, Mt, out);
}

// round 17
// speedup vs baseline: 3.7236x; 3.7236x over previous
#include <cuda_runtime.h>
#include <cstdint>

// Chamfer distance, B=4,S=4 pairs, N=M=4096 Gaussian 3D points.
// Warp-uniform 1-D sorted-window exact NN. QPT=2, 256-thr blocks, WIDE
// initial window (margin -6/+7 bins) so the ballot-expansion loop almost
// never iterates (certification radius ~ warp-max NN dist ~5 bins):
//  1) build_sorted: counting-sort the 32 lists by x into 256 bins over
//     [-5,5]; emits interleaved 32B records {x0,x1,y0,y1,z0,z1,h0,h1}
//     (h = 0.5*|p|^2) + u16 bin starts. Also zeroes d_out (block 0).
//  2) chamfer_query: block stages the packed target list (64KB) in smem.
//     Each warp owns 64 consecutive sorted queries (lane k: base+k and
//     base+32+k) -> 2 independent fma2 chains per lane. One long uniform
//     scan (2x LDS.128 + 6x fma2 + 4x FMNMX per record), then a ballot
//     check that rarely needs to expand.

#define BDIM 4
#define SDIM 4
#define NPAIRS 16
#define NB 256
#define MAXPTS 4096
#define NREC ((MAXPTS + 8) / 2)   /* 2052 records of 2 points */
#define GRIDMIN (-5.0f)
#define BW 0.0390625f             /* 10/256 */
#define INVBW 25.6f
#define QTHREADS 256
#define QPT 2
#define NCHUNK 8                  /* blocks per (dir,pair): 8*8 warps = 64 qgroups */

__device__ float g_packed[2 * NPAIRS][NREC * 8];
__device__ unsigned short g_start[2 * NPAIRS][NB + 1];

__device__ __forceinline__ uint64_t fma2(uint64_t a, uint64_t b, uint64_t c) {
    uint64_t d;
    asm("fma.rn.f32x2 %0, %1, %2, %3;" : "=l"(d) : "l"(a), "l"(b), "l"(c));
    return d;
}
__device__ __forceinline__ uint64_t pack2(float lo, float hi) {
    uint64_t d;
    asm("mov.b64 %0, {%1, %2};" : "=l"(d) : "f"(lo), "f"(hi));
    return d;
}
__device__ __forceinline__ void unpack2(uint64_t v, float& lo, float& hi) {
    asm("mov.b64 {%0, %1}, %2;" : "=f"(lo), "=f"(hi) : "l"(v));
}

// ---------------- counting sort by x into 256 bins ----------------
__global__ void build_sorted(const float* __restrict__ outp,
                             const float* __restrict__ tgtp,
                             int Nq, int Mt, float* __restrict__ out) {
    const int list = blockIdx.x;            // 0..31
    const int set = list >> 4, pair = list & 15;
    const float* pts = set ? tgtp : outp;
    const int n = set ? Mt : Nq;
    const float* base = pts + (size_t)pair * n * 3;

    if (list == 0 && threadIdx.x < BDIM * SDIM) out[threadIdx.x] = 0.f;

    __shared__ int cnt[NB];
    const int t = threadIdx.x;              // 256 threads

    cnt[t] = 0;
    __syncthreads();

    for (int i = t; i < n; i += NB) {
        float x = base[3 * i];
        int b = min(max(__float2int_rd((x - GRIDMIN) * INVBW), 0), NB - 1);
        atomicAdd(&cnt[b], 1);
    }
    __syncthreads();

    int v = cnt[t];
    __syncthreads();
#pragma unroll
    for (int off = 1; off < NB; off <<= 1) {
        int u = (t >= off) ? cnt[t - off] : 0;
        __syncthreads();
        cnt[t] += u;
        __syncthreads();
    }
    int start = cnt[t] - v;  // exclusive

    g_start[list][t] = (unsigned short)start;
    if (t == 0) g_start[list][NB] = (unsigned short)n;

    __syncthreads();
    cnt[t] = start;
    __syncthreads();

    for (int i = t; i < n; i += NB) {
        float x = base[3 * i], y = base[3 * i + 1], z = base[3 * i + 2];
        int b = min(max(__float2int_rd((x - GRIDMIN) * INVBW), 0), NB - 1);
        int idx = atomicAdd(&cnt[b], 1);
        float* rec = &g_packed[list][(idx >> 1) * 8];
        int s = idx & 1;
        rec[0 + s] = x;
        rec[2 + s] = y;
        rec[4 + s] = z;
        rec[6 + s] = 0.5f * (x * x + y * y + z * z);
    }
    // sentinel pad points [n, 2*NREC)
    for (int i = n + t; i < 2 * NREC; i += NB) {
        float* rec = &g_packed[list][(i >> 1) * 8];
        int s = i & 1;
        rec[0 + s] = 1e30f;
        rec[2 + s] = 0.f;
        rec[4 + s] = 0.f;
        rec[6 + s] = 3.0e37f;
    }
}

// ---------------- query ----------------
extern __shared__ char smraw[];

// warp-uniform scan of even point range [a,b); QPT independent chains/lane
__device__ __forceinline__ void scan_range(
    int a, int b,
    const uint64_t* nx, const uint64_t* ny, const uint64_t* nz,
    const ulonglong2* __restrict__ recs,
    float* mlo, float* mhi) {
    const int j0 = a >> 1, j1 = b >> 1;
#pragma unroll 2
    for (int j = j0; j < j1; j++) {
        ulonglong2 A = recs[2 * j];      // {x2, y2}
        ulonglong2 B = recs[2 * j + 1];  // {z2, h2}
#pragma unroll
        for (int k = 0; k < QPT; k++) {
            uint64_t t = fma2(nx[k], A.x, B.y);
            t = fma2(ny[k], A.y, t);
            t = fma2(nz[k], B.x, t);
            float lo, hi;
            unpack2(t, lo, hi);
            mlo[k] = fminf(mlo[k], lo);
            mhi[k] = fminf(mhi[k], hi);
        }
    }
}

__global__ __launch_bounds__(QTHREADS)
void chamfer_query(int Nq, int Mt, float* __restrict__ out) {
    const int dir = blockIdx.z;             // 0: out->tgt, 1: tgt->out
    const int pair = blockIdx.y;
    const int qlist = (dir ? NPAIRS : 0) + pair;      // own (sorted) set
    const int tlist = (dir ? 0 : NPAIRS) + pair;      // other set
    const int nq = dir ? Mt : Nq;

    // ---- stage packed target records (64KB copy) + bin starts ----
    uint4* dst = (uint4*)smraw;
    const uint4* src = (const uint4*)g_packed[tlist];
    for (int i = threadIdx.x; i < 2 * NREC; i += QTHREADS)
        dst[i] = src[i];
    unsigned short* sstart = (unsigned short*)(smraw + NREC * 32);
    for (int c = threadIdx.x; c <= NB; c += QTHREADS)
        sstart[c] = g_start[tlist][c];
    __syncthreads();

    const ulonglong2* recs = (const ulonglong2*)smraw;

    // warp w owns query-group (blockIdx.x + NCHUNK*w): 64 consecutive
    // sorted queries; lane k holds base+k and base+32+k.
    const int lwid = threadIdx.x >> 5;
    const int lane = threadIdx.x & 31;
    const int qgrp = blockIdx.x + NCHUNK * lwid;
    const int qbase = qgrp * (32 * QPT);

    float qx[QPT], q2[QPT], mlo[QPT], mhi[QPT];
    uint64_t nx[QPT], ny[QPT], nz[QPT];
    bool act[QPT];
    int bmin = 0x7fffffff, bmax = -1;
#pragma unroll
    for (int k = 0; k < QPT; k++) {
        int qi = qbase + 32 * k + lane;
        act[k] = (qi < nq);
        float a = 0.f, b = 0.f, c = 0.f;
        if (act[k]) {
            const float* qr = &g_packed[qlist][(qi >> 1) * 8];
            int s = qi & 1;
            a = qr[0 + s]; b = qr[2 + s]; c = qr[4 + s];
            int qb = min(max(__float2int_rd((a - GRIDMIN) * INVBW), 0), NB - 1);
            bmin = min(bmin, qb);
            bmax = max(bmax, qb);
        }
        qx[k] = a;
        q2[k] = a * a + b * b + c * c;
        nx[k] = pack2(-a, -a);
        ny[k] = pack2(-b, -b);
        nz[k] = pack2(-c, -c);
        mlo[k] = 3.0e37f;
        mhi[k] = 3.0e37f;
    }

    // warp-union window (warp-uniform); inactive lanes neutral
    int BL = bmin, BR = bmax;
#pragma unroll
    for (int off = 16; off; off >>= 1) {
        BL = min(BL, __shfl_xor_sync(0xffffffffu, BL, off));
        BR = max(BR, __shfl_xor_sync(0xffffffffu, BR, off));
    }

    if (BR >= 0) {  // warp has at least one active lane
        // WIDE initial margin: certification radius ~ warp-max NN dist
        // (~5 bins), so the expansion loop below almost never iterates.
        BL = max(BL - 6, 0);
        BR = min(BR + 7, NB);

        int LO = sstart[BL] & ~1;
        int HI = (sstart[BR] + 1) & ~1;
        scan_range(LO, HI, nx, ny, nz, recs, mlo, mhi);

        // ---- ballot-driven warp-uniform expansion (rare) ----
        for (int iter = 0; iter < NB; iter++) {
            bool needL = false, needR = false;
            float lbx = GRIDMIN + BL * BW;
            float rbx = GRIDMIN + BR * BW;
#pragma unroll
            for (int k = 0; k < QPT; k++) {
                float best = fmaxf(fmaf(2.0f, fminf(mlo[k], mhi[k]), q2[k]), 0.0f);
                float lb = fmaxf(qx[k] - lbx - 1e-4f, 0.0f);
                float rb = fmaxf(rbx - qx[k] - 1e-4f, 0.0f);
                needL |= act[k] && (lb * lb < best);
                needR |= act[k] && (rb * rb < best);
            }
            needL = needL && (BL > 0);
            needR = needR && (BR < NB);
            unsigned anyL = __ballot_sync(0xffffffffu, needL);
            unsigned anyR = __ballot_sync(0xffffffffu, needR);
            if (!anyL && !anyR) break;
            if (anyL) {
                int nBL = max(BL - 2, 0);
                int nLO = sstart[nBL] & ~1;
                scan_range(nLO, LO, nx, ny, nz, recs, mlo, mhi);
                BL = nBL; LO = nLO;
            }
            if (anyR) {
                int nBR = min(BR + 2, NB);
                int nHI = (sstart[nBR] + 1) & ~1;
                scan_range(HI, nHI, nx, ny, nz, recs, mlo, mhi);
                BR = nBR; HI = nHI;
            }
        }
    }

    float lsum = 0.f;
#pragma unroll
    for (int k = 0; k < QPT; k++)
        if (act[k])
            lsum += fmaxf(fmaf(2.0f, fminf(mlo[k], mhi[k]), q2[k]), 0.0f);

    // ---- block reduce + one atomicAdd ----
#pragma unroll
    for (int off = 16; off; off >>= 1)
        lsum += __shfl_down_sync(0xffffffffu, lsum, off);
    __shared__ float red[QTHREADS / 32];
    if ((threadIdx.x & 31) == 0) red[lwid] = lsum;
    __syncthreads();
    if (threadIdx.x == 0) {
        float tot = 0.f;
#pragma unroll
        for (int w = 0; w < QTHREADS / 32; w++) tot += red[w];
        int b = pair / SDIM;
        int s = pair % SDIM;
        atomicAdd(out + s * BDIM + b, tot / (float)nq);
    }
}

extern "C" void kernel_launch(void* const* d_in, const int* in_sizes, int n_in,
                              void* d_out, int out_size) {
    const float* outp = (const float*)d_in[0];  // [B,S,N,3]
    const float* tgtp = (const float*)d_in[1];  // [B,S,M,3]
    float* out = (float*)d_out;                  // [S,B]

    const int Nq = in_sizes[0] / (NPAIRS * 3);
    const int Mt = in_sizes[1] / (NPAIRS * 3);

    build_sorted<<<2 * NPAIRS, NB>>>(outp, tgtp, Nq, Mt, out);

    const size_t smem = (size_t)NREC * 32 + (NB + 2) * sizeof(unsigned short);
    cudaFuncSetAttribute(chamfer_query,
                         cudaFuncAttributeMaxDynamicSharedMemorySize, (int)smem);

    // NCHUNK blocks per (dir,pair); 8 warps/block stride the sorted order
    dim3 grid(NCHUNK, NPAIRS, 2);  // 256 blocks of 256 threads
    chamfer_query<<<grid, QTHREADS, smem>>>(Nq, Mt, out);
}